// round 15
// baseline (speedup 1.0000x reference)
#include <cuda_runtime.h>
#include <cstdint>

// Problem constants (fixed by setup_inputs): B=1, H=32, Lq=512, Lk=4096, group_size=4
#define H       32
#define LQ      512
#define LK      4096
#define WORDS   128            // LK / 32
#define KSEL    819            // int(0.2 * 4096)
#define THRESH  1638           // min(2*819, int(0.75*4096))
#define GS      4
#define NG      8              // H / GS
#define NOT_CHOSEN (1 << 30)
#define MAXCAND 64

// Raw-bits window for the 819th-largest of 4096 i.i.d. N(0,1) samples.
// Pivot concentrates at 0.8416 +- 0.022; [0.70, 1.00] is ~7 sigma. In-window
// values are positive floats => SIGNED int compares on raw bits are exact
// float compares (negatives are INT-negative => below any positive pivot).
// Bin width 2^14 ulps = 2^-10 in value; 308 bins. Exact fallback otherwise.
#define IWHI 0x3F800000        // bits(1.0f)
#define IWLO 0x3F333333        // bits(0.7f)
#define BSHIFT 14
#define HSIZE 320              // padded: 10 bins/lane * 32 lanes (308 used)
#define BPL 10

// Scratch (device globals; zero-init at load; no allocation allowed).
// g_bar1 is MONOTONIC: every execution adds exactly H, so "multiple of H"
// marks barrier completion; no reset needed across graph replays.
__device__ unsigned g_hunion[H * WORDS];
__device__ int      g_nsel[H];
__device__ unsigned g_bar1;

// Order-preserving float-bits <-> key map (exact-fallback path only)
__device__ __forceinline__ unsigned fkey_bits(unsigned u) {
    return (u & 0x80000000u) ? ~u : (u | 0x80000000u);
}
__device__ __forceinline__ int unfkey_bits(unsigned k) {
    return (int)((k & 0x80000000u) ? (k & 0x7FFFFFFFu) : ~k);
}

// Shared-memory state for one block of k_sel
struct ShState {
    unsigned hist[HSIZE];
    int      cand[MAXCAND];
    unsigned su[WORDS];        // running union bitset for this head
    unsigned s_cnthi, s_ncand, s_tot;
    int s_bin, s_rem, s_pivot, s_cnt, s_found, s_nstop;
};

// ---------------------------------------------------------------------------
// One row's exact top-k membership, ORed into S.su with incremental popcount
// into S.s_cnt. Champion (R12) row body: windowed 308-bin raw-int histogram,
// tiny exact refinement, exact binary-search fallback. 256 threads.
// ---------------------------------------------------------------------------
__device__ __forceinline__ void row_union(ShState& S, const int4* __restrict__ src,
                                          int t, int lane, int warp) {
    S.hist[t] = 0u;
    if (t < HSIZE - 256) S.hist[256 + t] = 0u;
    if (t == 0) { S.s_cnthi = 0u; S.s_ncand = 0u; S.s_bin = -2; }
    __syncthreads();

    // Load 16 elements/thread as raw bits (coalesced 16B)
    int ix[16];
    #pragma unroll
    for (int i = 0; i < 4; i++) {
        int4 v = src[t + i * 256];
        ix[4 * i + 0] = v.x; ix[4 * i + 1] = v.y;
        ix[4 * i + 2] = v.z; ix[4 * i + 3] = v.w;
    }

    // Count above-window; histogram in-window bits (~8% of row)
    int chi = 0;
    #pragma unroll
    for (int e = 0; e < 16; e++) {
        int k = ix[e];
        if (k > IWHI) chi++;
        else if (k >= IWLO) atomicAdd(&S.hist[(unsigned)(IWHI - k) >> BSHIFT], 1u);
    }
    #pragma unroll
    for (int off = 16; off; off >>= 1)
        chi += __shfl_down_sync(0xffffffffu, chi, off);
    if (lane == 0) atomicAdd(&S.s_cnthi, (unsigned)chi);
    __syncthreads();

    // One-warp cumulative-from-top scan over the bins (bin 0 = largest)
    if (warp == 0) {
        const unsigned cnthi = S.s_cnthi;
        unsigned part = 0;
        #pragma unroll
        for (int i = 0; i < BPL; i++) part += S.hist[lane * BPL + i];
        unsigned pfx = part;
        #pragma unroll
        for (int s = 1; s < 32; s <<= 1) {
            unsigned v = __shfl_up_sync(0xffffffffu, pfx, s);
            if (lane >= s) pfx += v;
        }
        unsigned excl  = pfx - part;
        unsigned total = __shfl_sync(0xffffffffu, pfx, 31);
        unsigned base  = cnthi + excl;
        if (base < KSEL && base + part >= KSEL) {
            unsigned acc = base;
            #pragma unroll
            for (int i = 0; i < BPL; i++) {
                unsigned hv = S.hist[lane * BPL + i];
                if (acc + hv >= KSEL) { S.s_bin = lane * BPL + i; S.s_rem = (int)(KSEL - acc); break; }
                acc += hv;
            }
        }
        if (lane == 0 && (cnthi >= KSEL || cnthi + total < KSEL)) S.s_bin = -1; // fallback
    }
    __syncthreads();

    const int bin = S.s_bin;
    if (bin >= 0) {
        // Gather pivot-bin candidates (expected ~1), exact rank-select
        #pragma unroll
        for (int e = 0; e < 16; e++) {
            int k = ix[e];
            if (k <= IWHI && k >= IWLO && (int)((unsigned)(IWHI - k) >> BSHIFT) == bin) {
                unsigned p = atomicAdd(&S.s_ncand, 1u);
                if (p < MAXCAND) S.cand[p] = k;
            }
        }
        __syncthreads();
        unsigned nc = S.s_ncand;
        if (nc <= MAXCAND) {
            const int rem = S.s_rem;
            if (t < (int)nc) {
                int me = S.cand[t];     // positive bits: signed cmp = float cmp
                int gcnt = 0, eq = 0;
                for (unsigned j = 0; j < nc; j++) {
                    int v = S.cand[j];
                    gcnt += (v > me);
                    eq   += (v == me);
                }
                if (gcnt < rem && gcnt + eq >= rem) S.s_pivot = me;
            }
        } else {
            if (t == 0) S.s_bin = -1;   // overflow -> fallback
        }
        __syncthreads();
    }

    if (S.s_bin < 0) {
        // Exact fallback: MSB-first binary search on order-preserving keys
        unsigned piv = 0;
        for (int bit = 31; bit >= 0; --bit) {
            unsigned candv = piv | (1u << bit);
            int c = 0;
            #pragma unroll
            for (int e = 0; e < 16; e++) c += (fkey_bits((unsigned)ix[e]) >= candv);
            #pragma unroll
            for (int off = 16; off; off >>= 1)
                c += __shfl_down_sync(0xffffffffu, c, off);
            if (t == 0) S.s_tot = 0u;
            __syncthreads();
            if (lane == 0) atomicAdd(&S.s_tot, (unsigned)c);
            __syncthreads();
            if (S.s_tot >= KSEL) piv = candv;
            __syncthreads();
        }
        if (t == 0) S.s_pivot = unfkey_bits(piv);
        __syncthreads();
    }

    const int pivot = S.s_pivot;

    // Membership nibbles -> octet-shuffle merge -> OR into union bitset,
    // incremental popcount into S.s_cnt (leaders own distinct words).
    #pragma unroll
    for (int i = 0; i < 4; i++) {
        unsigned nib = 0;
        #pragma unroll
        for (int m = 0; m < 4; m++) nib |= (unsigned)(ix[4 * i + m] >= pivot) << m;
        unsigned wv = nib << (4 * (lane & 7));
        wv |= __shfl_xor_sync(0xffffffffu, wv, 1);
        wv |= __shfl_xor_sync(0xffffffffu, wv, 2);
        wv |= __shfl_xor_sync(0xffffffffu, wv, 4);
        if ((lane & 7) == 0) {
            int idx = 32 * i + 4 * warp + (lane >> 3);
            unsigned old = S.su[idx];
            unsigned nw  = old | wv;
            if (nw != old) {
                S.su[idx] = nw;
                atomicAdd(&S.s_cnt, __popc(nw & ~old));
            }
        }
    }
    __syncthreads();
}

// ---------------------------------------------------------------------------
// Kernel 1: lazy back-to-front selection. One block per head; computes row
// top-k masks ON DEMAND from the last row backwards, stopping when the union
// reaches THRESH (~3 rows for this input; exact up to the full LQ scan for
// any input). One monotonic global barrier for the n_stop coupling, then
// extends the union to n_stop rows and publishes it.
// ---------------------------------------------------------------------------
__global__ void __launch_bounds__(256) k_sel(const float* __restrict__ scores) {
    __shared__ ShState S;
    const int h = blockIdx.x, t = threadIdx.x;
    const int lane = t & 31, warp = t >> 5;

    if (t < WORDS) S.su[t] = 0u;
    if (t == 0) { S.s_cnt = 0; S.s_found = 0; }
    __syncthreads();

    const int4* base = (const int4*)(scores + (size_t)h * LQ * LK);

    // Phase 1: scan from the back until the union reaches THRESH
    for (int n = 1; n <= LQ; n++) {
        row_union(S, base + (size_t)(LQ - n) * (LK / 4), t, lane, warp);
        if (t == 0 && !S.s_found && S.s_cnt >= THRESH) S.s_found = n;
        __syncthreads();
        if (S.s_found) break;           // uniform: decided from shared state
    }
    if (t == 0) {
        g_nsel[h] = S.s_found ? S.s_found : NOT_CHOSEN;
        __threadfence();
        atomicAdd(&g_bar1, 1u);
    }
    // Monotonic counter barrier across the 32 co-resident blocks: each
    // execution adds exactly H, so value % H == 0 <=> all arrived (polled
    // only after own arrival).
    if (t == 0) {
        volatile unsigned* vb = &g_bar1;
        while ((*vb & (H - 1)) != 0u) {}
    }
    __syncthreads();
    __threadfence();

    // n_stop = all heads chosen ? max(nsel) : LQ   (warp 0 computes)
    if (warp == 0) {
        int v  = g_nsel[lane];
        int ch = (v < NOT_CHOSEN) ? 1 : 0;
        int mx = ch ? v : 1;
        #pragma unroll
        for (int off = 16; off; off >>= 1) {
            ch = min(ch, __shfl_down_sync(0xffffffffu, ch, off));
            mx = max(mx, __shfl_down_sync(0xffffffffu, mx, off));
        }
        if (lane == 0) S.s_nstop = ch ? mx : LQ;
    }
    __syncthreads();

    // Phase 2: extend this head's union to cover the last n_stop rows
    const int ns    = S.s_nstop;
    const int start = (S.s_found ? S.s_found : LQ) + 1;
    for (int n = start; n <= ns; n++)
        row_union(S, base + (size_t)(LQ - n) * (LK / 4), t, lane, warp);

    if (t < WORDS) g_hunion[h * WORDS + t] = S.su[t];
}

// ---------------------------------------------------------------------------
// Kernel 2 (after the output memset): group-OR, last-row write, density.
// grid = H blocks, 256 threads; block h writes head h's last row.
// ---------------------------------------------------------------------------
__global__ void __launch_bounds__(256) k_fin(float* __restrict__ out, int write_density) {
    const int h = blockIdx.x, t = threadIdx.x;
    const int g = h / GS, lane = t & 31, warp = t >> 5;
    __shared__ unsigned su[WORDS];
    __shared__ int ws[8];

    if (t < WORDS)
        su[t] = g_hunion[(g * GS + 0) * WORDS + t]
              | g_hunion[(g * GS + 1) * WORDS + t]
              | g_hunion[(g * GS + 2) * WORDS + t]
              | g_hunion[(g * GS + 3) * WORDS + t];
    __syncthreads();

    const float MINV = -3.402823466e38f;  // finfo(float32).min
    float* orow = out + ((size_t)h * LQ + (LQ - 1)) * LK;
    #pragma unroll
    for (int i = 0; i < 4; i++) {
        int c4 = t + i * 256;              // float4 index; cols 4*c4..4*c4+3
        unsigned w = su[c4 >> 3];
        float4 v;
        v.x = ((w >> ((4 * c4 + 0) & 31)) & 1u) ? 0.0f : MINV;
        v.y = ((w >> ((4 * c4 + 1) & 31)) & 1u) ? 0.0f : MINV;
        v.z = ((w >> ((4 * c4 + 2) & 31)) & 1u) ? 0.0f : MINV;
        v.w = ((w >> ((4 * c4 + 3) & 31)) & 1u) ? 0.0f : MINV;
        ((float4*)orow)[c4] = v;
    }

    // Density over all 8 group unions (block 0 only; uniform per block)
    if (write_density && h == 0) {
        int c = 0;
        for (int p = t; p < NG * WORDS; p += 256) {
            int gg = p >> 7, w = p & 127;
            unsigned gu = g_hunion[(gg * GS + 0) * WORDS + w]
                        | g_hunion[(gg * GS + 1) * WORDS + w]
                        | g_hunion[(gg * GS + 2) * WORDS + w]
                        | g_hunion[(gg * GS + 3) * WORDS + w];
            c += __popc(gu);
        }
        #pragma unroll
        for (int off = 16; off; off >>= 1)
            c += __shfl_down_sync(0xffffffffu, c, off);
        if (lane == 0) ws[warp] = c;
        __syncthreads();
        if (t == 0) {
            int total = 0;
            #pragma unroll
            for (int w = 0; w < 8; w++) total += ws[w];
            out[(size_t)H * LQ * LK] = (float)(GS * total) / (float)(H * LK);
        }
    }
}

// ---------------------------------------------------------------------------
extern "C" void kernel_launch(void* const* d_in, const int* in_sizes, int n_in,
                              void* d_out, int out_size) {
    const float* scores = (const float*)d_in[0];
    float* out = (float*)d_out;

    k_sel<<<H, 256>>>(scores);                                   // ~4 MB of reads
    cudaMemsetAsync(d_out, 0, (size_t)out_size * sizeof(float), 0);  // the 256 MB
    k_fin<<<H, 256>>>(out, out_size > H * LQ * LK ? 1 : 0);      // last rows + density
}

// round 16
// speedup vs baseline: 1.0242x; 1.0242x over previous
#include <cuda_runtime.h>
#include <cstdint>

// Problem constants (fixed by setup_inputs): B=1, H=32, Lq=512, Lk=4096, group_size=4
#define H       32
#define LQ      512
#define LK      4096
#define WORDS   128            // LK / 32
#define KSEL    819            // int(0.2 * 4096)
#define THRESH  1638           // min(2*819, int(0.75*4096))
#define GS      4
#define NG      8              // H / GS
#define NOT_CHOSEN (1 << 30)
#define MAXCAND 64

// Raw-bits window for the 819th-largest of 4096 i.i.d. N(0,1) samples.
// Pivot concentrates at 0.8416 +- 0.022; [0.70, 1.00] is ~7 sigma. In-window
// values are positive floats => SIGNED int compares on raw bits are exact
// float compares (negatives are INT-negative => below any positive pivot).
// Bin width 2^14 ulps = 2^-10 in value; 308 bins. Exact fallback otherwise.
#define IWHI 0x3F800000        // bits(1.0f)
#define IWLO 0x3F333333        // bits(0.7f)
#define BSHIFT 14
#define HSIZE 320              // padded: 10 bins/lane * 32 lanes (308 used)
#define BPL 10

// Scratch (device globals; zero-init at load; no allocation allowed).
// g_bar1 is MONOTONIC: every execution adds exactly H, so "multiple of H"
// marks barrier completion; no reset needed across graph replays.
__device__ unsigned g_hunion[H * WORDS];
__device__ int      g_nsel[H];
__device__ unsigned g_bar1;

// Order-preserving float-bits <-> key map (exact-fallback path only)
__device__ __forceinline__ unsigned fkey_bits(unsigned u) {
    return (u & 0x80000000u) ? ~u : (u | 0x80000000u);
}
__device__ __forceinline__ int unfkey_bits(unsigned k) {
    return (int)((k & 0x80000000u) ? (k & 0x7FFFFFFFu) : ~k);
}

// Shared-memory state for one block of k_sel
struct ShState {
    unsigned hist[HSIZE];
    int      cand[MAXCAND];
    unsigned su[WORDS];        // running union bitset for this head
    unsigned s_cnthi, s_ncand, s_tot;
    int s_bin, s_rem, s_pivot, s_cnt, s_found, s_nstop;
};

// ---------------------------------------------------------------------------
// One row's exact top-k membership, ORed into S.su with incremental popcount
// into S.s_cnt. Champion (R12) row body: windowed 308-bin raw-int histogram,
// tiny exact refinement, exact binary-search fallback. 256 threads.
// ---------------------------------------------------------------------------
__device__ __forceinline__ void row_union(ShState& S, const int4* __restrict__ src,
                                          int t, int lane, int warp) {
    S.hist[t] = 0u;
    if (t < HSIZE - 256) S.hist[256 + t] = 0u;
    if (t == 0) { S.s_cnthi = 0u; S.s_ncand = 0u; S.s_bin = -2; }
    __syncthreads();

    // Load 16 elements/thread as raw bits (coalesced 16B)
    int ix[16];
    #pragma unroll
    for (int i = 0; i < 4; i++) {
        int4 v = src[t + i * 256];
        ix[4 * i + 0] = v.x; ix[4 * i + 1] = v.y;
        ix[4 * i + 2] = v.z; ix[4 * i + 3] = v.w;
    }

    // Count above-window; histogram in-window bits (~8% of row)
    int chi = 0;
    #pragma unroll
    for (int e = 0; e < 16; e++) {
        int k = ix[e];
        if (k > IWHI) chi++;
        else if (k >= IWLO) atomicAdd(&S.hist[(unsigned)(IWHI - k) >> BSHIFT], 1u);
    }
    #pragma unroll
    for (int off = 16; off; off >>= 1)
        chi += __shfl_down_sync(0xffffffffu, chi, off);
    if (lane == 0) atomicAdd(&S.s_cnthi, (unsigned)chi);
    __syncthreads();

    // One-warp cumulative-from-top scan over the bins (bin 0 = largest)
    if (warp == 0) {
        const unsigned cnthi = S.s_cnthi;
        unsigned part = 0;
        #pragma unroll
        for (int i = 0; i < BPL; i++) part += S.hist[lane * BPL + i];
        unsigned pfx = part;
        #pragma unroll
        for (int s = 1; s < 32; s <<= 1) {
            unsigned v = __shfl_up_sync(0xffffffffu, pfx, s);
            if (lane >= s) pfx += v;
        }
        unsigned excl  = pfx - part;
        unsigned total = __shfl_sync(0xffffffffu, pfx, 31);
        unsigned base  = cnthi + excl;
        if (base < KSEL && base + part >= KSEL) {
            unsigned acc = base;
            #pragma unroll
            for (int i = 0; i < BPL; i++) {
                unsigned hv = S.hist[lane * BPL + i];
                if (acc + hv >= KSEL) { S.s_bin = lane * BPL + i; S.s_rem = (int)(KSEL - acc); break; }
                acc += hv;
            }
        }
        if (lane == 0 && (cnthi >= KSEL || cnthi + total < KSEL)) S.s_bin = -1; // fallback
    }
    __syncthreads();

    const int bin = S.s_bin;
    if (bin >= 0) {
        // Gather pivot-bin candidates (expected ~1), exact rank-select
        #pragma unroll
        for (int e = 0; e < 16; e++) {
            int k = ix[e];
            if (k <= IWHI && k >= IWLO && (int)((unsigned)(IWHI - k) >> BSHIFT) == bin) {
                unsigned p = atomicAdd(&S.s_ncand, 1u);
                if (p < MAXCAND) S.cand[p] = k;
            }
        }
        __syncthreads();
        unsigned nc = S.s_ncand;
        if (nc <= MAXCAND) {
            const int rem = S.s_rem;
            if (t < (int)nc) {
                int me = S.cand[t];     // positive bits: signed cmp = float cmp
                int gcnt = 0, eq = 0;
                for (unsigned j = 0; j < nc; j++) {
                    int v = S.cand[j];
                    gcnt += (v > me);
                    eq   += (v == me);
                }
                if (gcnt < rem && gcnt + eq >= rem) S.s_pivot = me;
            }
        } else {
            if (t == 0) S.s_bin = -1;   // overflow -> fallback
        }
        __syncthreads();
    }

    if (S.s_bin < 0) {
        // Exact fallback: MSB-first binary search on order-preserving keys
        unsigned piv = 0;
        for (int bit = 31; bit >= 0; --bit) {
            unsigned candv = piv | (1u << bit);
            int c = 0;
            #pragma unroll
            for (int e = 0; e < 16; e++) c += (fkey_bits((unsigned)ix[e]) >= candv);
            #pragma unroll
            for (int off = 16; off; off >>= 1)
                c += __shfl_down_sync(0xffffffffu, c, off);
            if (t == 0) S.s_tot = 0u;
            __syncthreads();
            if (lane == 0) atomicAdd(&S.s_tot, (unsigned)c);
            __syncthreads();
            if (S.s_tot >= KSEL) piv = candv;
            __syncthreads();
        }
        if (t == 0) S.s_pivot = unfkey_bits(piv);
        __syncthreads();
    }

    const int pivot = S.s_pivot;

    // Membership nibbles -> octet-shuffle merge -> OR into union bitset,
    // incremental popcount into S.s_cnt (leaders own distinct words).
    #pragma unroll
    for (int i = 0; i < 4; i++) {
        unsigned nib = 0;
        #pragma unroll
        for (int m = 0; m < 4; m++) nib |= (unsigned)(ix[4 * i + m] >= pivot) << m;
        unsigned wv = nib << (4 * (lane & 7));
        wv |= __shfl_xor_sync(0xffffffffu, wv, 1);
        wv |= __shfl_xor_sync(0xffffffffu, wv, 2);
        wv |= __shfl_xor_sync(0xffffffffu, wv, 4);
        if ((lane & 7) == 0) {
            int idx = 32 * i + 4 * warp + (lane >> 3);
            unsigned old = S.su[idx];
            unsigned nw  = old | wv;
            if (nw != old) {
                S.su[idx] = nw;
                atomicAdd(&S.s_cnt, __popc(nw & ~old));
            }
        }
    }
    __syncthreads();
}

// ---------------------------------------------------------------------------
// Kernel 1: lazy back-to-front selection. One block per head; computes row
// top-k masks ON DEMAND from the last row backwards, stopping when the union
// reaches THRESH (~3 rows for this input; exact up to the full LQ scan for
// any input). One monotonic global barrier for the n_stop coupling, then
// extends the union to n_stop rows and publishes it.
// ---------------------------------------------------------------------------
__global__ void __launch_bounds__(256) k_sel(const float* __restrict__ scores) {
    __shared__ ShState S;
    const int h = blockIdx.x, t = threadIdx.x;
    const int lane = t & 31, warp = t >> 5;

    if (t < WORDS) S.su[t] = 0u;
    if (t == 0) { S.s_cnt = 0; S.s_found = 0; }
    __syncthreads();

    const int4* base = (const int4*)(scores + (size_t)h * LQ * LK);

    // Phase 1: scan from the back until the union reaches THRESH
    for (int n = 1; n <= LQ; n++) {
        row_union(S, base + (size_t)(LQ - n) * (LK / 4), t, lane, warp);
        if (t == 0 && !S.s_found && S.s_cnt >= THRESH) S.s_found = n;
        __syncthreads();
        if (S.s_found) break;           // uniform: decided from shared state
    }
    if (t == 0) {
        g_nsel[h] = S.s_found ? S.s_found : NOT_CHOSEN;
        __threadfence();
        atomicAdd(&g_bar1, 1u);
    }
    // Monotonic counter barrier across the 32 co-resident blocks: each
    // execution adds exactly H, so value % H == 0 <=> all arrived (polled
    // only after own arrival).
    if (t == 0) {
        volatile unsigned* vb = &g_bar1;
        while ((*vb & (H - 1)) != 0u) {}
    }
    __syncthreads();
    __threadfence();

    // n_stop = all heads chosen ? max(nsel) : LQ   (warp 0 computes)
    if (warp == 0) {
        int v  = g_nsel[lane];
        int ch = (v < NOT_CHOSEN) ? 1 : 0;
        int mx = ch ? v : 1;
        #pragma unroll
        for (int off = 16; off; off >>= 1) {
            ch = min(ch, __shfl_down_sync(0xffffffffu, ch, off));
            mx = max(mx, __shfl_down_sync(0xffffffffu, mx, off));
        }
        if (lane == 0) S.s_nstop = ch ? mx : LQ;
    }
    __syncthreads();

    // Phase 2: extend this head's union to cover the last n_stop rows
    const int ns    = S.s_nstop;
    const int start = (S.s_found ? S.s_found : LQ) + 1;
    for (int n = start; n <= ns; n++)
        row_union(S, base + (size_t)(LQ - n) * (LK / 4), t, lane, warp);

    if (t < WORDS) g_hunion[h * WORDS + t] = S.su[t];
}

// ---------------------------------------------------------------------------
// Kernel 2 (after the output memset): group-OR, last-row write, density.
// grid = H blocks, 256 threads; block h writes head h's last row.
// ---------------------------------------------------------------------------
__global__ void __launch_bounds__(256) k_fin(float* __restrict__ out, int write_density) {
    const int h = blockIdx.x, t = threadIdx.x;
    const int g = h / GS, lane = t & 31, warp = t >> 5;
    __shared__ unsigned su[WORDS];
    __shared__ int ws[8];

    if (t < WORDS)
        su[t] = g_hunion[(g * GS + 0) * WORDS + t]
              | g_hunion[(g * GS + 1) * WORDS + t]
              | g_hunion[(g * GS + 2) * WORDS + t]
              | g_hunion[(g * GS + 3) * WORDS + t];
    __syncthreads();

    const float MINV = -3.402823466e38f;  // finfo(float32).min
    float* orow = out + ((size_t)h * LQ + (LQ - 1)) * LK;
    #pragma unroll
    for (int i = 0; i < 4; i++) {
        int c4 = t + i * 256;              // float4 index; cols 4*c4..4*c4+3
        unsigned w = su[c4 >> 3];
        float4 v;
        v.x = ((w >> ((4 * c4 + 0) & 31)) & 1u) ? 0.0f : MINV;
        v.y = ((w >> ((4 * c4 + 1) & 31)) & 1u) ? 0.0f : MINV;
        v.z = ((w >> ((4 * c4 + 2) & 31)) & 1u) ? 0.0f : MINV;
        v.w = ((w >> ((4 * c4 + 3) & 31)) & 1u) ? 0.0f : MINV;
        ((float4*)orow)[c4] = v;
    }

    // Density over all 8 group unions (block 0 only; uniform per block)
    if (write_density && h == 0) {
        int c = 0;
        for (int p = t; p < NG * WORDS; p += 256) {
            int gg = p >> 7, w = p & 127;
            unsigned gu = g_hunion[(gg * GS + 0) * WORDS + w]
                        | g_hunion[(gg * GS + 1) * WORDS + w]
                        | g_hunion[(gg * GS + 2) * WORDS + w]
                        | g_hunion[(gg * GS + 3) * WORDS + w];
            c += __popc(gu);
        }
        #pragma unroll
        for (int off = 16; off; off >>= 1)
            c += __shfl_down_sync(0xffffffffu, c, off);
        if (lane == 0) ws[warp] = c;
        __syncthreads();
        if (t == 0) {
            int total = 0;
            #pragma unroll
            for (int w = 0; w < 8; w++) total += ws[w];
            out[(size_t)H * LQ * LK] = (float)(GS * total) / (float)(H * LK);
        }
    }
}

// ---------------------------------------------------------------------------
extern "C" void kernel_launch(void* const* d_in, const int* in_sizes, int n_in,
                              void* d_out, int out_size) {
    const float* scores = (const float*)d_in[0];
    float* out = (float*)d_out;

    k_sel<<<H, 256>>>(scores);                                   // ~4 MB of reads
    cudaMemsetAsync(d_out, 0, (size_t)out_size * sizeof(float), 0);  // the 256 MB
    k_fin<<<H, 256>>>(out, out_size > H * LQ * LK ? 1 : 0);      // last rows + density
}

// round 17
// speedup vs baseline: 1.2433x; 1.2140x over previous
#include <cuda_runtime.h>
#include <cstdint>

// Problem constants (fixed by setup_inputs): B=1, H=32, Lq=512, Lk=4096, group_size=4
#define H       32
#define LQ      512
#define LK      4096
#define WORDS   128            // LK / 32
#define KSEL    819            // int(0.2 * 4096)
#define THRESH  1638           // min(2*819, int(0.75*4096))
#define GS      4
#define NG      8              // H / GS
#define NOT_CHOSEN (1 << 30)
#define MAXCAND 64
#define NZROWS  (H * (LQ - 1)) // 16352 non-last rows, zeroed by worker blocks
#define GRID    (H + NZROWS)   // 16384 blocks total

// Raw-bits window for the 819th-largest of 4096 i.i.d. N(0,1) samples.
// Pivot concentrates at 0.8416 +- 0.022; [0.70, 1.00] is ~7 sigma. In-window
// values are positive floats => SIGNED int compares on raw bits are exact
// float compares (negatives are INT-negative => below any positive pivot).
// Bin width 2^14 ulps = 2^-10 in value; 308 bins. Exact fallback otherwise.
#define IWHI 0x3F800000        // bits(1.0f)
#define IWLO 0x3F333333        // bits(0.7f)
#define BSHIFT 14
#define HSIZE 320              // padded: 10 bins/lane * 32 lanes (308 used)
#define BPL 10

// Scratch (device globals; zero-init at load; no allocation allowed).
// g_bar1/g_bar2 are MONOTONIC: every execution adds exactly H to each, so
// "value % H == 0" (polled only after own arrival) marks barrier completion;
// no reset needed across graph replays.
__device__ unsigned g_hunion[H * WORDS];
__device__ int      g_nsel[H];
__device__ unsigned g_bar1, g_bar2;

// Order-preserving float-bits <-> key map (exact-fallback path only)
__device__ __forceinline__ unsigned fkey_bits(unsigned u) {
    return (u & 0x80000000u) ? ~u : (u | 0x80000000u);
}
__device__ __forceinline__ int unfkey_bits(unsigned k) {
    return (int)((k & 0x80000000u) ? (k & 0x7FFFFFFFu) : ~k);
}

// Shared-memory state for one selection block
struct ShState {
    unsigned hist[HSIZE];
    int      cand[MAXCAND];
    unsigned su[WORDS];        // running union bitset for this head
    unsigned s_cnthi, s_ncand, s_tot;
    int s_bin, s_rem, s_pivot, s_cnt, s_found, s_nstop;
};

// ---------------------------------------------------------------------------
// One row's exact top-k membership, ORed into S.su with incremental popcount
// into S.s_cnt. Champion row body: windowed 308-bin raw-int histogram, tiny
// exact refinement, exact binary-search fallback. 256 threads.
// ---------------------------------------------------------------------------
__device__ __forceinline__ void row_union(ShState& S, const int4* __restrict__ src,
                                          int t, int lane, int warp) {
    S.hist[t] = 0u;
    if (t < HSIZE - 256) S.hist[256 + t] = 0u;
    if (t == 0) { S.s_cnthi = 0u; S.s_ncand = 0u; S.s_bin = -2; }
    __syncthreads();

    // Load 16 elements/thread as raw bits (coalesced 16B)
    int ix[16];
    #pragma unroll
    for (int i = 0; i < 4; i++) {
        int4 v = src[t + i * 256];
        ix[4 * i + 0] = v.x; ix[4 * i + 1] = v.y;
        ix[4 * i + 2] = v.z; ix[4 * i + 3] = v.w;
    }

    // Count above-window; histogram in-window bits (~8% of row)
    int chi = 0;
    #pragma unroll
    for (int e = 0; e < 16; e++) {
        int k = ix[e];
        if (k > IWHI) chi++;
        else if (k >= IWLO) atomicAdd(&S.hist[(unsigned)(IWHI - k) >> BSHIFT], 1u);
    }
    #pragma unroll
    for (int off = 16; off; off >>= 1)
        chi += __shfl_down_sync(0xffffffffu, chi, off);
    if (lane == 0) atomicAdd(&S.s_cnthi, (unsigned)chi);
    __syncthreads();

    // One-warp cumulative-from-top scan over the bins (bin 0 = largest)
    if (warp == 0) {
        const unsigned cnthi = S.s_cnthi;
        unsigned part = 0;
        #pragma unroll
        for (int i = 0; i < BPL; i++) part += S.hist[lane * BPL + i];
        unsigned pfx = part;
        #pragma unroll
        for (int s = 1; s < 32; s <<= 1) {
            unsigned v = __shfl_up_sync(0xffffffffu, pfx, s);
            if (lane >= s) pfx += v;
        }
        unsigned excl  = pfx - part;
        unsigned total = __shfl_sync(0xffffffffu, pfx, 31);
        unsigned base  = cnthi + excl;
        if (base < KSEL && base + part >= KSEL) {
            unsigned acc = base;
            #pragma unroll
            for (int i = 0; i < BPL; i++) {
                unsigned hv = S.hist[lane * BPL + i];
                if (acc + hv >= KSEL) { S.s_bin = lane * BPL + i; S.s_rem = (int)(KSEL - acc); break; }
                acc += hv;
            }
        }
        if (lane == 0 && (cnthi >= KSEL || cnthi + total < KSEL)) S.s_bin = -1; // fallback
    }
    __syncthreads();

    const int bin = S.s_bin;
    if (bin >= 0) {
        // Gather pivot-bin candidates (expected ~1), exact rank-select
        #pragma unroll
        for (int e = 0; e < 16; e++) {
            int k = ix[e];
            if (k <= IWHI && k >= IWLO && (int)((unsigned)(IWHI - k) >> BSHIFT) == bin) {
                unsigned p = atomicAdd(&S.s_ncand, 1u);
                if (p < MAXCAND) S.cand[p] = k;
            }
        }
        __syncthreads();
        unsigned nc = S.s_ncand;
        if (nc <= MAXCAND) {
            const int rem = S.s_rem;
            if (t < (int)nc) {
                int me = S.cand[t];     // positive bits: signed cmp = float cmp
                int gcnt = 0, eq = 0;
                for (unsigned j = 0; j < nc; j++) {
                    int v = S.cand[j];
                    gcnt += (v > me);
                    eq   += (v == me);
                }
                if (gcnt < rem && gcnt + eq >= rem) S.s_pivot = me;
            }
        } else {
            if (t == 0) S.s_bin = -1;   // overflow -> fallback
        }
        __syncthreads();
    }

    if (S.s_bin < 0) {
        // Exact fallback: MSB-first binary search on order-preserving keys
        unsigned piv = 0;
        for (int bit = 31; bit >= 0; --bit) {
            unsigned candv = piv | (1u << bit);
            int c = 0;
            #pragma unroll
            for (int e = 0; e < 16; e++) c += (fkey_bits((unsigned)ix[e]) >= candv);
            #pragma unroll
            for (int off = 16; off; off >>= 1)
                c += __shfl_down_sync(0xffffffffu, c, off);
            if (t == 0) S.s_tot = 0u;
            __syncthreads();
            if (lane == 0) atomicAdd(&S.s_tot, (unsigned)c);
            __syncthreads();
            if (S.s_tot >= KSEL) piv = candv;
            __syncthreads();
        }
        if (t == 0) S.s_pivot = unfkey_bits(piv);
        __syncthreads();
    }

    const int pivot = S.s_pivot;

    // Membership nibbles -> octet-shuffle merge -> OR into union bitset,
    // incremental popcount into S.s_cnt (leaders own distinct words).
    #pragma unroll
    for (int i = 0; i < 4; i++) {
        unsigned nib = 0;
        #pragma unroll
        for (int m = 0; m < 4; m++) nib |= (unsigned)(ix[4 * i + m] >= pivot) << m;
        unsigned wv = nib << (4 * (lane & 7));
        wv |= __shfl_xor_sync(0xffffffffu, wv, 1);
        wv |= __shfl_xor_sync(0xffffffffu, wv, 2);
        wv |= __shfl_xor_sync(0xffffffffu, wv, 4);
        if ((lane & 7) == 0) {
            int idx = 32 * i + 4 * warp + (lane >> 3);
            unsigned old = S.su[idx];
            unsigned nw  = old | wv;
            if (nw != old) {
                S.su[idx] = nw;
                atomicAdd(&S.s_cnt, __popc(nw & ~old));
            }
        }
    }
    __syncthreads();
}

// ---------------------------------------------------------------------------
// ONE fused kernel, one wave. Blocks 0..H-1 (first-wave resident, so spin
// barriers are safe): lazy back-to-front per-head selection -> n_stop
// coupling -> union -> group-OR -> write head's LAST row + density.
// Blocks H..GRID-1: zero one non-last output row each (the 255.5 MB stream),
// running concurrently with the selection.
// ---------------------------------------------------------------------------
__global__ void __launch_bounds__(256) k_all(const float* __restrict__ scores,
                                             float* __restrict__ out,
                                             int write_density) {
    const int bid = blockIdx.x;
    const int t   = threadIdx.x;

    if (bid >= H) {
        // ---- zero worker: one non-last row (h, q), 16 KB of streaming zeros
        const int r = bid - H;                 // 0 .. NZROWS-1
        const int h = r / (LQ - 1);
        const int q = r % (LQ - 1);
        float4* dst = (float4*)(out + ((size_t)h * LQ + q) * LK);
        const float4 z = make_float4(0.f, 0.f, 0.f, 0.f);
        #pragma unroll
        for (int i = 0; i < 4; i++) __stcs(dst + t + i * 256, z);
        return;
    }

    // ---- selection block for head h ----
    __shared__ ShState S;
    const int h = bid;
    const int g = h / GS;
    const int lane = t & 31, warp = t >> 5;

    if (t < WORDS) S.su[t] = 0u;
    if (t == 0) { S.s_cnt = 0; S.s_found = 0; }
    __syncthreads();

    const int4* base = (const int4*)(scores + (size_t)h * LQ * LK);

    // Phase 1: scan from the back until the union reaches THRESH (~3 rows)
    for (int n = 1; n <= LQ; n++) {
        row_union(S, base + (size_t)(LQ - n) * (LK / 4), t, lane, warp);
        if (t == 0 && !S.s_found && S.s_cnt >= THRESH) S.s_found = n;
        __syncthreads();
        if (S.s_found) break;           // uniform: decided from shared state
    }
    if (t == 0) {
        g_nsel[h] = S.s_found ? S.s_found : NOT_CHOSEN;
        __threadfence();
        atomicAdd(&g_bar1, 1u);
    }
    // Monotonic counter barrier 1 (32 first-wave-resident blocks)
    if (t == 0) {
        volatile unsigned* vb = &g_bar1;
        while ((*vb & (H - 1)) != 0u) {}
    }
    __syncthreads();
    __threadfence();

    // n_stop = all heads chosen ? max(nsel) : LQ   (warp 0 computes)
    if (warp == 0) {
        int v  = g_nsel[lane];
        int ch = (v < NOT_CHOSEN) ? 1 : 0;
        int mx = ch ? v : 1;
        #pragma unroll
        for (int off = 16; off; off >>= 1) {
            ch = min(ch, __shfl_down_sync(0xffffffffu, ch, off));
            mx = max(mx, __shfl_down_sync(0xffffffffu, mx, off));
        }
        if (lane == 0) S.s_nstop = ch ? mx : LQ;
    }
    __syncthreads();

    // Phase 2: extend this head's union to cover the last n_stop rows
    const int ns    = S.s_nstop;
    const int start = (S.s_found ? S.s_found : LQ) + 1;
    for (int n = start; n <= ns; n++)
        row_union(S, base + (size_t)(LQ - n) * (LK / 4), t, lane, warp);

    if (t < WORDS) g_hunion[h * WORDS + t] = S.su[t];
    __threadfence();
    __syncthreads();
    if (t == 0) atomicAdd(&g_bar2, 1u);
    // Monotonic counter barrier 2
    if (t == 0) {
        volatile unsigned* vb = &g_bar2;
        while ((*vb & (H - 1)) != 0u) {}
    }
    __syncthreads();
    __threadfence();

    // Group-OR for this head's group (re-using S.su as the group union)
    if (t < WORDS)
        S.su[t] = g_hunion[(g * GS + 0) * WORDS + t]
                | g_hunion[(g * GS + 1) * WORDS + t]
                | g_hunion[(g * GS + 2) * WORDS + t]
                | g_hunion[(g * GS + 3) * WORDS + t];
    __syncthreads();

    // Write head h's LAST row from the group union (16 KB, float4)
    const float MINV = -3.402823466e38f;  // finfo(float32).min
    float* orow = out + ((size_t)h * LQ + (LQ - 1)) * LK;
    #pragma unroll
    for (int i = 0; i < 4; i++) {
        int c4 = t + i * 256;              // float4 index; cols 4*c4..4*c4+3
        unsigned w = S.su[c4 >> 3];
        float4 v;
        v.x = ((w >> ((4 * c4 + 0) & 31)) & 1u) ? 0.0f : MINV;
        v.y = ((w >> ((4 * c4 + 1) & 31)) & 1u) ? 0.0f : MINV;
        v.z = ((w >> ((4 * c4 + 2) & 31)) & 1u) ? 0.0f : MINV;
        v.w = ((w >> ((4 * c4 + 3) & 31)) & 1u) ? 0.0f : MINV;
        __stcs((float4*)orow + c4, v);
    }

    // Density over all 8 group unions (head-0 block only)
    if (write_density && h == 0) {
        __shared__ int ws[8];
        int c = 0;
        for (int p = t; p < NG * WORDS; p += 256) {
            int gg = p >> 7, w = p & 127;
            unsigned gu = g_hunion[(gg * GS + 0) * WORDS + w]
                        | g_hunion[(gg * GS + 1) * WORDS + w]
                        | g_hunion[(gg * GS + 2) * WORDS + w]
                        | g_hunion[(gg * GS + 3) * WORDS + w];
            c += __popc(gu);
        }
        #pragma unroll
        for (int off = 16; off; off >>= 1)
            c += __shfl_down_sync(0xffffffffu, c, off);
        if (lane == 0) ws[warp] = c;
        __syncthreads();
        if (t == 0) {
            int total = 0;
            #pragma unroll
            for (int w = 0; w < 8; w++) total += ws[w];
            out[(size_t)H * LQ * LK] = (float)(GS * total) / (float)(H * LK);
        }
    }
}

// ---------------------------------------------------------------------------
extern "C" void kernel_launch(void* const* d_in, const int* in_sizes, int n_in,
                              void* d_out, int out_size) {
    const float* scores = (const float*)d_in[0];
    float* out = (float*)d_out;
    k_all<<<GRID, 256>>>(scores, out, out_size > H * LQ * LK ? 1 : 0);
}